// round 2
// baseline (speedup 1.0000x reference)
#include <cuda_runtime.h>
#include <cstddef>

#define BATCH 1024
#define SIZE  65536
#define DIM   512
#define NS    16            // split-S factor
#define BM    32            // queries per CTA
#define BN    32            // memory rows per tile
#define TPB   256
#define SSTRIDE 516         // 512 + 4 words pad: conflict-free float4 LDS
#define CHUNK (SIZE / NS)   // 4096 rows per split

// ---- scratch (allocation-free: __device__ globals) ----
__device__ float g_minv[SIZE];
__device__ float g_xinv[BATCH];
__device__ float g_part[(size_t)NS * BATCH * DIM];   // 32 MB partial outputs
__device__ float g_sm[NS * BATCH];                   // running max per split
__device__ float g_sl[NS * BATCH];                   // running sumexp per split

// ---------------------------------------------------------------------------
// Kernel 1: per-row inverse L2 norm. One warp per row (512 floats = 16/lane).
// rows==SIZE -> writes g_minv, else g_xinv (avoids host symbol lookups).
// ---------------------------------------------------------------------------
__global__ void rownorm_kernel(const float* __restrict__ A, int rows) {
    int row = blockIdx.x * 8 + (threadIdx.x >> 5);
    int l   = threadIdx.x & 31;
    if (row >= rows) return;
    const float4* a = reinterpret_cast<const float4*>(A + (size_t)row * DIM);
    float ss = 0.f;
#pragma unroll
    for (int j = 0; j < 4; ++j) {
        float4 v = a[l + 32 * j];
        ss += v.x * v.x + v.y * v.y + v.z * v.z + v.w * v.w;
    }
#pragma unroll
    for (int o = 16; o; o >>= 1) ss += __shfl_xor_sync(0xffffffffu, ss, o);
    if (l == 0) {
        float inv = rsqrtf(fmaxf(ss, 1e-24f));
        if (rows == SIZE) g_minv[row] = inv;
        else              g_xinv[row] = inv;
    }
}

// ---------------------------------------------------------------------------
// Kernel 2: fused flash attention over the memory bank.
// grid = (BATCH/BM, NS). blockIdx.x = query block (fast dim -> L2 tile reuse
// across concurrent CTAs), blockIdx.y = S-split.
// Warp w owns queries 4w..4w+3; lane l owns sims column r=l; for the output
// GEMM lane l owns d in {4l+128j}. P values broadcast intra-warp via shfl.
// ---------------------------------------------------------------------------
__global__ __launch_bounds__(TPB, 1) void flash_kernel(
    const float* __restrict__ x, const float* __restrict__ mb) {
    extern __shared__ float smem[];
    float* xs = smem;                 // [BM][SSTRIDE]
    float* ms = smem + BM * SSTRIDE;  // [BN][SSTRIDE]

    const int qb  = blockIdx.x;
    const int sp  = blockIdx.y;
    const int tid = threadIdx.x;
    const int w   = tid >> 5;
    const int l   = tid & 31;

    // stage x block, pre-scaled by 8 / ||x_q||  (temperature folded in)
    for (int i = tid; i < BM * (DIM / 4); i += TPB) {
        int r = i >> 7, c = i & 127;
        float4 v = reinterpret_cast<const float4*>(x)[(size_t)(qb * BM + r) * (DIM / 4) + c];
        float s = 8.0f * g_xinv[qb * BM + r];
        v.x *= s; v.y *= s; v.z *= s; v.w *= s;
        *reinterpret_cast<float4*>(&xs[r * SSTRIDE + 4 * c]) = v;
    }

    float4 acc[4][4];
#pragma unroll
    for (int qi = 0; qi < 4; ++qi)
#pragma unroll
        for (int j = 0; j < 4; ++j) acc[qi][j] = make_float4(0.f, 0.f, 0.f, 0.f);
    float mrun[4], lrun[4];
#pragma unroll
    for (int qi = 0; qi < 4; ++qi) { mrun[qi] = -1e30f; lrun[qi] = 0.f; }

    const int row0 = sp * CHUNK;
    for (int t = 0; t < CHUNK / BN; ++t) {
        const int rbase = row0 + t * BN;
        __syncthreads();   // protects xs (1st iter) and ms reuse (later iters)
        for (int i = tid; i < BN * (DIM / 4); i += TPB) {
            int r = i >> 7, c = i & 127;
            float4 v = reinterpret_cast<const float4*>(mb)[(size_t)(rbase + r) * (DIM / 4) + c];
            *reinterpret_cast<float4*>(&ms[r * SSTRIDE + 4 * c]) = v;
        }
        __syncthreads();

        // ---- sims: dot(q, row l) for 4 queries ----
        float dot[4] = {0.f, 0.f, 0.f, 0.f};
#pragma unroll 4
        for (int d4 = 0; d4 < DIM / 4; ++d4) {
            float4 mv = *reinterpret_cast<const float4*>(&ms[l * SSTRIDE + 4 * d4]);
#pragma unroll
            for (int qi = 0; qi < 4; ++qi) {
                float4 xv = *reinterpret_cast<const float4*>(&xs[(4 * w + qi) * SSTRIDE + 4 * d4]);
                dot[qi] += xv.x * mv.x;
                dot[qi] += xv.y * mv.y;
                dot[qi] += xv.z * mv.z;
                dot[qi] += xv.w * mv.w;
            }
        }
        const float minv = g_minv[rbase + l];

        // ---- online softmax (row = warp) ----
        float p[4];
#pragma unroll
        for (int qi = 0; qi < 4; ++qi) {
            float lg = dot[qi] * minv;
            float tmax = lg;
#pragma unroll
            for (int o = 16; o; o >>= 1)
                tmax = fmaxf(tmax, __shfl_xor_sync(0xffffffffu, tmax, o));
            float nm = fmaxf(mrun[qi], tmax);
            float pv = __expf(lg - nm);
            float ts = pv;
#pragma unroll
            for (int o = 16; o; o >>= 1) ts += __shfl_xor_sync(0xffffffffu, ts, o);
            float alpha = __expf(mrun[qi] - nm);
            lrun[qi] = lrun[qi] * alpha + ts;
            mrun[qi] = nm;
#pragma unroll
            for (int j = 0; j < 4; ++j) {
                acc[qi][j].x *= alpha; acc[qi][j].y *= alpha;
                acc[qi][j].z *= alpha; acc[qi][j].w *= alpha;
            }
            p[qi] = pv;
        }

        // ---- output accumulation: acc += P @ ms (P broadcast via shfl) ----
#pragma unroll 8
        for (int r = 0; r < BN; ++r) {
            float pq[4];
#pragma unroll
            for (int qi = 0; qi < 4; ++qi)
                pq[qi] = __shfl_sync(0xffffffffu, p[qi], r);
#pragma unroll
            for (int j = 0; j < 4; ++j) {
                float4 mv = *reinterpret_cast<const float4*>(&ms[r * SSTRIDE + 4 * l + 128 * j]);
#pragma unroll
                for (int qi = 0; qi < 4; ++qi) {
                    acc[qi][j].x += pq[qi] * mv.x;
                    acc[qi][j].y += pq[qi] * mv.y;
                    acc[qi][j].z += pq[qi] * mv.z;
                    acc[qi][j].w += pq[qi] * mv.w;
                }
            }
        }
    }

    // ---- write split partials + stats ----
#pragma unroll
    for (int qi = 0; qi < 4; ++qi) {
        int q = qb * BM + 4 * w + qi;
        float* dst = &g_part[((size_t)sp * BATCH + q) * DIM];
#pragma unroll
        for (int j = 0; j < 4; ++j)
            *reinterpret_cast<float4*>(&dst[4 * l + 128 * j]) = acc[qi][j];
        if (l == 0) {
            g_sm[sp * BATCH + q] = mrun[qi];
            g_sl[sp * BATCH + q] = lrun[qi];
        }
    }
}

// ---------------------------------------------------------------------------
// Kernel 3: combine NS split partials per query.
// ---------------------------------------------------------------------------
__global__ void combine_kernel(float* __restrict__ out) {
    const int q = blockIdx.x;
    __shared__ float wsh[NS];
    __shared__ float invL;
    if (threadIdx.x == 0) {
        float M = -1e30f;
#pragma unroll
        for (int i = 0; i < NS; ++i) M = fmaxf(M, g_sm[i * BATCH + q]);
        float L = 0.f;
#pragma unroll
        for (int i = 0; i < NS; ++i) {
            float wi = __expf(g_sm[i * BATCH + q] - M);
            wsh[i] = wi;
            L += wi * g_sl[i * BATCH + q];
        }
        invL = 1.0f / L;
    }
    __syncthreads();
    const int d = threadIdx.x * 2;   // 256 threads x 2 floats = 512
    float sx = 0.f, sy = 0.f;
#pragma unroll
    for (int i = 0; i < NS; ++i) {
        const float2 v = *reinterpret_cast<const float2*>(
            &g_part[((size_t)i * BATCH + q) * DIM + d]);
        sx += wsh[i] * v.x;
        sy += wsh[i] * v.y;
    }
    float il = invL;
    float2 o; o.x = sx * il; o.y = sy * il;
    *reinterpret_cast<float2*>(&out[(size_t)q * DIM + d]) = o;
}

// ---------------------------------------------------------------------------
extern "C" void kernel_launch(void* const* d_in, const int* in_sizes, int n_in,
                              void* d_out, int out_size) {
    const float* x  = (const float*)d_in[0];
    const float* mb = (const float*)d_in[1];
    float* out = (float*)d_out;

    const int FLASH_SMEM = 2 * BM * SSTRIDE * (int)sizeof(float);  // 132096 B
    static int attr_done = 0;
    // idempotent host-side attribute set (not a stream op; capture-safe)
    cudaFuncSetAttribute(flash_kernel,
                         cudaFuncAttributeMaxDynamicSharedMemorySize, FLASH_SMEM);
    (void)attr_done; (void)in_sizes; (void)n_in; (void)out_size;

    rownorm_kernel<<<SIZE / 8, 256>>>(mb, SIZE);
    rownorm_kernel<<<BATCH / 8, 256>>>(x, BATCH);
    flash_kernel<<<dim3(BATCH / BM, NS), TPB, FLASH_SMEM>>>(x, mb);
    combine_kernel<<<BATCH, 256>>>(out);
}

// round 3
// speedup vs baseline: 1.0009x; 1.0009x over previous
#include <cuda_runtime.h>
#include <cstddef>

#define BATCH 1024
#define SIZE  65536
#define DIM   512
#define NS    16            // split-S factor
#define BM    32            // queries per CTA
#define BN    32            // memory rows per tile
#define TPB   256
#define SSTRIDE 516         // 512 + 4 words pad: conflict-free float4 LDS
#define CHUNK (SIZE / NS)   // 4096 rows per split

// ---- scratch (allocation-free: __device__ globals) ----
__device__ float g_minv[SIZE];
__device__ float g_xinv[BATCH];
__device__ float g_part[(size_t)NS * BATCH * DIM];   // 32 MB partial outputs
__device__ float g_sm[NS * BATCH];                   // running max per split
__device__ float g_sl[NS * BATCH];                   // running sumexp per split

// ---------------------------------------------------------------------------
// Kernel 1: per-row inverse L2 norm. One warp per row (512 floats = 16/lane).
// rows==SIZE -> writes g_minv, else g_xinv (avoids host symbol lookups).
// ---------------------------------------------------------------------------
__global__ void rownorm_kernel(const float* __restrict__ A, int rows) {
    int row = blockIdx.x * 8 + (threadIdx.x >> 5);
    int l   = threadIdx.x & 31;
    if (row >= rows) return;
    const float4* a = reinterpret_cast<const float4*>(A + (size_t)row * DIM);
    float ss = 0.f;
#pragma unroll
    for (int j = 0; j < 4; ++j) {
        float4 v = a[l + 32 * j];
        ss += v.x * v.x + v.y * v.y + v.z * v.z + v.w * v.w;
    }
#pragma unroll
    for (int o = 16; o; o >>= 1) ss += __shfl_xor_sync(0xffffffffu, ss, o);
    if (l == 0) {
        float inv = rsqrtf(fmaxf(ss, 1e-24f));
        if (rows == SIZE) g_minv[row] = inv;
        else              g_xinv[row] = inv;
    }
}

// ---------------------------------------------------------------------------
// Kernel 2: fused flash attention over the memory bank.
// grid = (BATCH/BM, NS). blockIdx.x = query block (fast dim -> L2 tile reuse
// across concurrent CTAs), blockIdx.y = S-split.
// Warp w owns queries 4w..4w+3; lane l owns sims column r=l; for the output
// GEMM lane l owns d in {4l+128j}. P values broadcast intra-warp via shfl.
// ---------------------------------------------------------------------------
__global__ __launch_bounds__(TPB, 1) void flash_kernel(
    const float* __restrict__ x, const float* __restrict__ mb) {
    extern __shared__ float smem[];
    float* xs = smem;                 // [BM][SSTRIDE]
    float* ms = smem + BM * SSTRIDE;  // [BN][SSTRIDE]

    const int qb  = blockIdx.x;
    const int sp  = blockIdx.y;
    const int tid = threadIdx.x;
    const int w   = tid >> 5;
    const int l   = tid & 31;

    // stage x block, pre-scaled by 8 / ||x_q||  (temperature folded in)
    for (int i = tid; i < BM * (DIM / 4); i += TPB) {
        int r = i >> 7, c = i & 127;
        float4 v = reinterpret_cast<const float4*>(x)[(size_t)(qb * BM + r) * (DIM / 4) + c];
        float s = 8.0f * g_xinv[qb * BM + r];
        v.x *= s; v.y *= s; v.z *= s; v.w *= s;
        *reinterpret_cast<float4*>(&xs[r * SSTRIDE + 4 * c]) = v;
    }

    float4 acc[4][4];
#pragma unroll
    for (int qi = 0; qi < 4; ++qi)
#pragma unroll
        for (int j = 0; j < 4; ++j) acc[qi][j] = make_float4(0.f, 0.f, 0.f, 0.f);
    float mrun[4], lrun[4];
#pragma unroll
    for (int qi = 0; qi < 4; ++qi) { mrun[qi] = -1e30f; lrun[qi] = 0.f; }

    const int row0 = sp * CHUNK;
    for (int t = 0; t < CHUNK / BN; ++t) {
        const int rbase = row0 + t * BN;
        __syncthreads();   // protects xs (1st iter) and ms reuse (later iters)
        for (int i = tid; i < BN * (DIM / 4); i += TPB) {
            int r = i >> 7, c = i & 127;
            float4 v = reinterpret_cast<const float4*>(mb)[(size_t)(rbase + r) * (DIM / 4) + c];
            *reinterpret_cast<float4*>(&ms[r * SSTRIDE + 4 * c]) = v;
        }
        __syncthreads();

        // ---- sims: dot(q, row l) for 4 queries ----
        float dot[4] = {0.f, 0.f, 0.f, 0.f};
#pragma unroll 4
        for (int d4 = 0; d4 < DIM / 4; ++d4) {
            float4 mv = *reinterpret_cast<const float4*>(&ms[l * SSTRIDE + 4 * d4]);
#pragma unroll
            for (int qi = 0; qi < 4; ++qi) {
                float4 xv = *reinterpret_cast<const float4*>(&xs[(4 * w + qi) * SSTRIDE + 4 * d4]);
                dot[qi] += xv.x * mv.x;
                dot[qi] += xv.y * mv.y;
                dot[qi] += xv.z * mv.z;
                dot[qi] += xv.w * mv.w;
            }
        }
        const float minv = g_minv[rbase + l];

        // ---- online softmax (row = warp) ----
        float p[4];
#pragma unroll
        for (int qi = 0; qi < 4; ++qi) {
            float lg = dot[qi] * minv;
            float tmax = lg;
#pragma unroll
            for (int o = 16; o; o >>= 1)
                tmax = fmaxf(tmax, __shfl_xor_sync(0xffffffffu, tmax, o));
            float nm = fmaxf(mrun[qi], tmax);
            float pv = __expf(lg - nm);
            float ts = pv;
#pragma unroll
            for (int o = 16; o; o >>= 1) ts += __shfl_xor_sync(0xffffffffu, ts, o);
            float alpha = __expf(mrun[qi] - nm);
            lrun[qi] = lrun[qi] * alpha + ts;
            mrun[qi] = nm;
#pragma unroll
            for (int j = 0; j < 4; ++j) {
                acc[qi][j].x *= alpha; acc[qi][j].y *= alpha;
                acc[qi][j].z *= alpha; acc[qi][j].w *= alpha;
            }
            p[qi] = pv;
        }

        // ---- output accumulation: acc += P @ ms (P broadcast via shfl) ----
#pragma unroll 8
        for (int r = 0; r < BN; ++r) {
            float pq[4];
#pragma unroll
            for (int qi = 0; qi < 4; ++qi)
                pq[qi] = __shfl_sync(0xffffffffu, p[qi], r);
#pragma unroll
            for (int j = 0; j < 4; ++j) {
                float4 mv = *reinterpret_cast<const float4*>(&ms[r * SSTRIDE + 4 * l + 128 * j]);
#pragma unroll
                for (int qi = 0; qi < 4; ++qi) {
                    acc[qi][j].x += pq[qi] * mv.x;
                    acc[qi][j].y += pq[qi] * mv.y;
                    acc[qi][j].z += pq[qi] * mv.z;
                    acc[qi][j].w += pq[qi] * mv.w;
                }
            }
        }
    }

    // ---- write split partials + stats ----
#pragma unroll
    for (int qi = 0; qi < 4; ++qi) {
        int q = qb * BM + 4 * w + qi;
        float* dst = &g_part[((size_t)sp * BATCH + q) * DIM];
#pragma unroll
        for (int j = 0; j < 4; ++j)
            *reinterpret_cast<float4*>(&dst[4 * l + 128 * j]) = acc[qi][j];
        if (l == 0) {
            g_sm[sp * BATCH + q] = mrun[qi];
            g_sl[sp * BATCH + q] = lrun[qi];
        }
    }
}

// ---------------------------------------------------------------------------
// Kernel 3: combine NS split partials per query.
// ---------------------------------------------------------------------------
__global__ void combine_kernel(float* __restrict__ out) {
    const int q = blockIdx.x;
    __shared__ float wsh[NS];
    __shared__ float invL;
    if (threadIdx.x == 0) {
        float M = -1e30f;
#pragma unroll
        for (int i = 0; i < NS; ++i) M = fmaxf(M, g_sm[i * BATCH + q]);
        float L = 0.f;
#pragma unroll
        for (int i = 0; i < NS; ++i) {
            float wi = __expf(g_sm[i * BATCH + q] - M);
            wsh[i] = wi;
            L += wi * g_sl[i * BATCH + q];
        }
        invL = 1.0f / L;
    }
    __syncthreads();
    const int d = threadIdx.x * 2;   // 256 threads x 2 floats = 512
    float sx = 0.f, sy = 0.f;
#pragma unroll
    for (int i = 0; i < NS; ++i) {
        const float2 v = *reinterpret_cast<const float2*>(
            &g_part[((size_t)i * BATCH + q) * DIM + d]);
        sx += wsh[i] * v.x;
        sy += wsh[i] * v.y;
    }
    float il = invL;
    float2 o; o.x = sx * il; o.y = sy * il;
    *reinterpret_cast<float2*>(&out[(size_t)q * DIM + d]) = o;
}

// ---------------------------------------------------------------------------
extern "C" void kernel_launch(void* const* d_in, const int* in_sizes, int n_in,
                              void* d_out, int out_size) {
    const float* x  = (const float*)d_in[0];
    const float* mb = (const float*)d_in[1];
    float* out = (float*)d_out;

    const int FLASH_SMEM = 2 * BM * SSTRIDE * (int)sizeof(float);  // 132096 B
    static int attr_done = 0;
    // idempotent host-side attribute set (not a stream op; capture-safe)
    cudaFuncSetAttribute(flash_kernel,
                         cudaFuncAttributeMaxDynamicSharedMemorySize, FLASH_SMEM);
    (void)attr_done; (void)in_sizes; (void)n_in; (void)out_size;

    rownorm_kernel<<<SIZE / 8, 256>>>(mb, SIZE);
    rownorm_kernel<<<BATCH / 8, 256>>>(x, BATCH);
    flash_kernel<<<dim3(BATCH / BM, NS), TPB, FLASH_SMEM>>>(x, mb);
    combine_kernel<<<BATCH, 256>>>(out);
}

// round 5
// speedup vs baseline: 6.2170x; 6.2115x over previous
#include <cuda_runtime.h>
#include <cstdint>
#include <cstddef>

#define BATCH 1024
#define SIZE  65536
#define DIM   512
#define SPLITS 16
#define KSPLIT (SIZE / SPLITS)      // 4096

#define TS 40                        // smem tile row stride in floats (32 data + 8 pad)
#define TILE_BYTES (128 * TS * 4)    // 20480
#define STAGE_BYTES (2 * TILE_BYTES) // 40960 (A+B)
#define SMEM_BYTES (2 * STAGE_BYTES) // 81920 (double buffered)
#define NCH1 (DIM / 32)              // 16 k-chunks in GEMM1
#define NCH2 (KSPLIT / 32)           // 128 k-chunks per GEMM2 CTA

// ---------------- device scratch (allocation-free) ----------------
__device__ float g_minv[SIZE];
__device__ float g_xinv[BATCH];
__device__ float g_xp[(size_t)BATCH * DIM];           //   2 MB  x scaled+rounded, k-perm
__device__ float g_mb1[(size_t)SIZE * DIM];           // 128 MB  mb rounded, k-perm (GEMM1 B)
__device__ float g_mbT[(size_t)DIM * SIZE];           // 128 MB  mb^T rounded, k-perm (GEMM2 B)
__device__ float g_P[(size_t)BATCH * SIZE];           // 256 MB  exp(sims), k-perm (GEMM2 A)
__device__ float g_Lpart[(size_t)(SIZE / 128) * BATCH]; // 2 MB  per-nCTA row sums
__device__ float g_part2[(size_t)SPLITS * BATCH * DIM]; // 32 MB split-K partials

// ---------------- helpers ----------------
__device__ __forceinline__ uint32_t smem_to_u32(const void* p) {
    uint32_t a;
    asm("{ .reg .u64 t; cvta.to.shared.u64 t, %1; cvt.u32.u64 %0, t; }" : "=r"(a) : "l"(p));
    return a;
}
__device__ __forceinline__ void cp16(uint32_t s, const void* g) {
    asm volatile("cp.async.cg.shared.global [%0], [%1], 16;" :: "r"(s), "l"(g));
}
__device__ __forceinline__ void cp_commit() { asm volatile("cp.async.commit_group;"); }
__device__ __forceinline__ float tf32r(float x) {
    uint32_t u;
    asm("cvt.rna.tf32.f32 %0, %1;" : "=r"(u) : "f"(x));
    return __uint_as_float(u);
}
// k-column micro-permutation within each 8-group: logical i -> phys (i<4 ? 2i : 2i-7)
// makes fragment pairs (k, k+4) physically adjacent => LDS.64 fragment loads.
__device__ __forceinline__ int perm8(int i) { return (i < 4) ? 2 * i : 2 * i - 7; }

__device__ __forceinline__ void mma_tf32(float* c, float2 a01, float2 a13, float2 b01) {
    asm volatile(
        "mma.sync.aligned.m16n8k8.row.col.f32.tf32.tf32.f32 "
        "{%0,%1,%2,%3}, {%4,%5,%6,%7}, {%8,%9}, {%0,%1,%2,%3};"
        : "+f"(c[0]), "+f"(c[1]), "+f"(c[2]), "+f"(c[3])
        : "r"(__float_as_uint(a01.x)), "r"(__float_as_uint(a13.x)),
          "r"(__float_as_uint(a01.y)), "r"(__float_as_uint(a13.y)),
          "r"(__float_as_uint(b01.x)), "r"(__float_as_uint(b01.y)));
}

// ---------------- kernel 1: inverse row norms ----------------
__global__ void rownorm_kernel(const float* __restrict__ A, int rows) {
    int row = blockIdx.x * 8 + (threadIdx.x >> 5);
    int l = threadIdx.x & 31;
    if (row >= rows) return;
    const float4* a = reinterpret_cast<const float4*>(A + (size_t)row * DIM);
    float ss = 0.f;
#pragma unroll
    for (int j = 0; j < 4; ++j) {
        float4 v = a[l + 32 * j];
        ss += v.x * v.x + v.y * v.y + v.z * v.z + v.w * v.w;
    }
#pragma unroll
    for (int o = 16; o; o >>= 1) ss += __shfl_xor_sync(0xffffffffu, ss, o);
    if (l == 0) {
        float inv = rsqrtf(fmaxf(ss, 1e-24f));
        if (rows == SIZE) g_minv[row] = inv; else g_xinv[row] = inv;
    }
}

// ---------------- kernel 2: pack x (scaled by 8/||x||, rounded, k-perm) ----------------
__global__ void pack_x_kernel(const float* __restrict__ x) {
    int idx = blockIdx.x * 256 + threadIdx.x;   // BATCH*DIM
    int m = idx >> 9, d = idx & 511;
    float v = tf32r(x[idx] * 8.0f * g_xinv[m]);
    g_xp[(size_t)m * DIM + (d & ~7) + perm8(d & 7)] = v;
}

// ---------------- kernel 3: pack mb -> g_mb1 and g_mbT (rounded, k-perm) ----------------
__global__ void pack_mb_kernel(const float* __restrict__ mbk) {
    __shared__ float t[32][33];
    int s0 = blockIdx.x << 5, d0 = blockIdx.y << 5;
    int tx = threadIdx.x & 31, ty = threadIdx.x >> 5;   // 256 threads
#pragma unroll
    for (int k = 0; k < 4; ++k) {
        int s = s0 + ty + (k << 3);
        float v = tf32r(mbk[(size_t)s * DIM + d0 + tx]);
        t[ty + (k << 3)][tx] = v;
        g_mb1[(size_t)s * DIM + d0 + (tx & ~7) + perm8(tx & 7)] = v;
    }
    __syncthreads();
#pragma unroll
    for (int k = 0; k < 4; ++k) {
        int d = d0 + ty + (k << 3);
        float v = t[tx][ty + (k << 3)];
        g_mbT[(size_t)d * SIZE + s0 + (tx & ~7) + perm8(tx & 7)] = v;
    }
}

// ---------------- shared GEMM machinery ----------------
__device__ __forceinline__ void load_tiles(uint32_t sbase,
                                           const float* __restrict__ Ag,
                                           const float* __restrict__ Bg,
                                           size_t arow, size_t brow, int kpos, int tid) {
#pragma unroll
    for (int j = 0; j < 4; ++j) {
        int i = tid + 256 * j;          // 1024 granules of 16B for A
        int row = i >> 3, gg = i & 7;
        cp16(sbase + row * (TS * 4) + gg * 16, Ag + (size_t)row * arow + kpos + gg * 4);
    }
#pragma unroll
    for (int j = 0; j < 4; ++j) {
        int i = tid + 256 * j;
        int row = i >> 3, gg = i & 7;
        cp16(sbase + TILE_BYTES + row * (TS * 4) + gg * 16,
             Bg + (size_t)row * brow + kpos + gg * 4);
    }
}

__device__ __forceinline__ void compute_chunk(const float* __restrict__ As,
                                              const float* __restrict__ Bs,
                                              int wm, int wn, int g, int tg,
                                              float c[2][8][4]) {
    const float* Aw = As + (wm * 32 + g) * TS + 2 * tg;
    const float* Bw = Bs + (wn * 64 + g) * TS + 2 * tg;
#pragma unroll
    for (int k8 = 0; k8 < 32; k8 += 8) {
        float2 a01[2], a13[2], bf[8];
#pragma unroll
        for (int mt = 0; mt < 2; ++mt) {
            a01[mt] = *(const float2*)(Aw + (mt * 16) * TS + k8);
            a13[mt] = *(const float2*)(Aw + (mt * 16 + 8) * TS + k8);
        }
#pragma unroll
        for (int nt = 0; nt < 8; ++nt)
            bf[nt] = *(const float2*)(Bw + (nt * 8) * TS + k8);
#pragma unroll
        for (int mt = 0; mt < 2; ++mt)
#pragma unroll
            for (int nt = 0; nt < 8; ++nt)
                mma_tf32(c[mt][nt], a01[mt], a13[mt], bf[nt]);
    }
}

__device__ __forceinline__ void gemm_mainloop(char* smc, uint32_t sm32,
                                              const float* __restrict__ Ag,
                                              const float* __restrict__ Bg,
                                              size_t arow, size_t brow,
                                              int kbase, int nch, int tid,
                                              int wm, int wn, int g, int tg,
                                              float c[2][8][4]) {
    load_tiles(sm32, Ag, Bg, arow, brow, kbase, tid);
    cp_commit();
    for (int t = 0; t < nch; ++t) {
        __syncthreads();   // all threads done with buffer (t+1)&1 from iter t-1
        if (t + 1 < nch) {
            load_tiles(sm32 + ((t + 1) & 1) * STAGE_BYTES, Ag, Bg, arow, brow,
                       kbase + (t + 1) * 32, tid);
            cp_commit();
            asm volatile("cp.async.wait_group 1;");
        } else {
            asm volatile("cp.async.wait_group 0;");
        }
        __syncthreads();   // chunk t visible to all threads
        const float* As = (const float*)(smc + (t & 1) * STAGE_BYTES);
        const float* Bs = As + TILE_BYTES / 4;
        compute_chunk(As, Bs, wm, wn, g, tg, c);
    }
}

// ---------------- kernel 4: GEMM1 sims + exp epilogue -> g_P, g_Lpart ----------------
__global__ __launch_bounds__(256, 2) void gemm1_kernel() {
    extern __shared__ char smc[];
    uint32_t sm32 = smem_to_u32(smc);
    int tid = threadIdx.x, lane = tid & 31, w = tid >> 5;
    int wm = w & 3, wn = w >> 2, g = lane >> 2, tg = lane & 3;
    int mblk = blockIdx.x, nblk = blockIdx.y;

    float c[2][8][4];
#pragma unroll
    for (int mt = 0; mt < 2; ++mt)
#pragma unroll
        for (int nt = 0; nt < 8; ++nt)
#pragma unroll
            for (int i = 0; i < 4; ++i) c[mt][nt][i] = 0.f;

    gemm_mainloop(smc, sm32,
                  g_xp + (size_t)mblk * 128 * DIM,
                  g_mb1 + (size_t)nblk * 128 * DIM,
                  DIM, DIM, 0, NCH1, tid, wm, wn, g, tg, c);

    // ---- epilogue: logits -> exp -> store P (+ deterministic row sums) ----
    __syncthreads();                        // done with tile smem; reuse it
    float* minv_s = (float*)smc;            // [128] logical-col m-norms
    float* smL = (float*)(smc + 512);       // [2][128] per-wn row sums
    if (tid < 128) minv_s[tid] = g_minv[nblk * 128 + tid];
    __syncthreads();

    float sl[2] = {0.f, 0.f}, sh[2] = {0.f, 0.f};
    int p0 = (tg < 2) ? 4 * tg : 4 * tg - 7;   // phys col of logical 2*tg
#pragma unroll
    for (int mt = 0; mt < 2; ++mt) {
        size_t brow0 = (size_t)(mblk * 128 + wm * 32 + mt * 16 + g) * SIZE;
        size_t brow8 = brow0 + (size_t)8 * SIZE;
#pragma unroll
        for (int nt = 0; nt < 8; ++nt) {
            int col0 = wn * 64 + nt * 8 + 2 * tg;          // logical
            float m0 = minv_s[col0], m1 = minv_s[col0 + 1];
            float e0 = __expf(c[mt][nt][0] * m0);
            float e1 = __expf(c[mt][nt][1] * m1);
            float e2 = __expf(c[mt][nt][2] * m0);
            float e3 = __expf(c[mt][nt][3] * m1);
            sl[mt] += e0 + e1;
            sh[mt] += e2 + e3;
            size_t sb = (size_t)nblk * 128 + wn * 64 + nt * 8;
            g_P[brow0 + sb + p0]     = e0;
            g_P[brow0 + sb + p0 + 2] = e1;
            g_P[brow8 + sb + p0]     = e2;
            g_P[brow8 + sb + p0 + 2] = e3;
        }
    }
#pragma unroll
    for (int mt = 0; mt < 2; ++mt) {
        float vl = sl[mt], vh = sh[mt];
        vl += __shfl_xor_sync(0xffffffffu, vl, 1);
        vl += __shfl_xor_sync(0xffffffffu, vl, 2);
        vh += __shfl_xor_sync(0xffffffffu, vh, 1);
        vh += __shfl_xor_sync(0xffffffffu, vh, 2);
        if (tg == 0) {
            smL[wn * 128 + wm * 32 + mt * 16 + g] = vl;
            smL[wn * 128 + wm * 32 + mt * 16 + g + 8] = vh;
        }
    }
    __syncthreads();
    if (tid < 128)
        g_Lpart[(size_t)nblk * BATCH + mblk * 128 + tid] = smL[tid] + smL[128 + tid];
}

// ---------------- kernel 5: GEMM2 O = P @ mb (split-K partials) ----------------
__global__ __launch_bounds__(256, 2) void gemm2_kernel() {
    extern __shared__ char smc[];
    uint32_t sm32 = smem_to_u32(smc);
    int tid = threadIdx.x, lane = tid & 31, w = tid >> 5;
    int wm = w & 3, wn = w >> 2, g = lane >> 2, tg = lane & 3;
    int mblk = blockIdx.x, nblk = blockIdx.y, sp = blockIdx.z;

    float c[2][8][4];
#pragma unroll
    for (int mt = 0; mt < 2; ++mt)
#pragma unroll
        for (int nt = 0; nt < 8; ++nt)
#pragma unroll
            for (int i = 0; i < 4; ++i) c[mt][nt][i] = 0.f;

    gemm_mainloop(smc, sm32,
                  g_P + (size_t)mblk * 128 * SIZE,
                  g_mbT + (size_t)nblk * 128 * SIZE,
                  SIZE, SIZE, sp * KSPLIT, NCH2, tid, wm, wn, g, tg, c);

#pragma unroll
    for (int mt = 0; mt < 2; ++mt) {
        int b = mblk * 128 + wm * 32 + mt * 16 + g;
#pragma unroll
        for (int nt = 0; nt < 8; ++nt) {
            int d = nblk * 128 + wn * 64 + nt * 8 + 2 * tg;
            float* dst = &g_part2[((size_t)sp * BATCH + b) * DIM + d];
            *(float2*)dst = make_float2(c[mt][nt][0], c[mt][nt][1]);
            *(float2*)(dst + (size_t)8 * DIM) = make_float2(c[mt][nt][2], c[mt][nt][3]);
        }
    }
}

// ---------------- kernel 6: combine split-K partials, divide by L ----------------
__global__ void combine_kernel(float* __restrict__ out) {
    int b = blockIdx.x, tid = threadIdx.x;   // 128 threads
    __shared__ float red[128];
    float ls = 0.f;
#pragma unroll
    for (int k = 0; k < 4; ++k) ls += g_Lpart[(size_t)(k * 128 + tid) * BATCH + b];
    red[tid] = ls;
    __syncthreads();
    for (int o = 64; o; o >>= 1) { if (tid < o) red[tid] += red[tid + o]; __syncthreads(); }
    float invL = 1.0f / red[0];
    int d = tid * 4;
    float4 acc = make_float4(0.f, 0.f, 0.f, 0.f);
#pragma unroll
    for (int sp = 0; sp < SPLITS; ++sp) {
        const float4 v = *(const float4*)&g_part2[((size_t)sp * BATCH + b) * DIM + d];
        acc.x += v.x; acc.y += v.y; acc.z += v.z; acc.w += v.w;
    }
    acc.x *= invL; acc.y *= invL; acc.z *= invL; acc.w *= invL;
    *(float4*)&out[(size_t)b * DIM + d] = acc;
}

// ---------------------------------------------------------------------------
extern "C" void kernel_launch(void* const* d_in, const int* in_sizes, int n_in,
                              void* d_out, int out_size) {
    const float* x = (const float*)d_in[0];
    const float* mb = (const float*)d_in[1];
    float* out = (float*)d_out;
    (void)in_sizes; (void)n_in; (void)out_size;

    cudaFuncSetAttribute(gemm1_kernel, cudaFuncAttributeMaxDynamicSharedMemorySize, SMEM_BYTES);
    cudaFuncSetAttribute(gemm2_kernel, cudaFuncAttributeMaxDynamicSharedMemorySize, SMEM_BYTES);

    rownorm_kernel<<<SIZE / 8, 256>>>(mb, SIZE);
    rownorm_kernel<<<BATCH / 8, 256>>>(x, BATCH);
    pack_x_kernel<<<(BATCH * DIM) / 256, 256>>>(x);
    pack_mb_kernel<<<dim3(SIZE / 32, DIM / 32), 256>>>(mb);
    gemm1_kernel<<<dim3(BATCH / 128, SIZE / 128), 256, SMEM_BYTES>>>();
    gemm2_kernel<<<dim3(BATCH / 128, DIM / 128, SPLITS), 256, SMEM_BYTES>>>();
    combine_kernel<<<BATCH, 128>>>(out);
}

// round 6
// speedup vs baseline: 10.9575x; 1.7625x over previous
#include <cuda_runtime.h>
#include <cuda_fp16.h>
#include <cstdint>
#include <cstddef>

#define BATCH 1024
#define SIZE  65536
#define DIM   512
#define SPLITS 32
#define KSPLIT (SIZE / SPLITS)        // 2048

#define RSTRIDE 96                    // smem row stride in BYTES (32 halfs data + pad)
#define TILE_BYTES (128 * RSTRIDE)    // 12288
#define STAGE_BYTES (2 * TILE_BYTES)  // 24576 (A+B)
#define SMEM_BYTES (3 * STAGE_BYTES)  // 73728 (3-stage)
#define NCH1 (DIM / 32)               // 16 k-chunks in GEMM1
#define NCH2 (KSPLIT / 32)            // 64 k-chunks per GEMM2 CTA

// ---------------- device scratch (allocation-free) ----------------
__device__ float g_minv[SIZE];
__device__ float g_xinv[BATCH];
__device__ __align__(16) __half g_xp[(size_t)BATCH * DIM];     //   1 MB
__device__ __align__(16) __half g_mb1[(size_t)SIZE * DIM];     //  64 MB (GEMM1 B)
__device__ __align__(16) __half g_mbT[(size_t)DIM * SIZE];     //  64 MB (GEMM2 B)
__device__ __align__(16) __half g_P[(size_t)BATCH * SIZE];     // 128 MB (GEMM2 A)
__device__ float g_Lpart[(size_t)(SIZE / 128) * BATCH];        //   2 MB
__device__ float g_part2[(size_t)SPLITS * BATCH * DIM];        //  64 MB

// ---------------- helpers ----------------
__device__ __forceinline__ uint32_t smem_to_u32(const void* p) {
    uint32_t a;
    asm("{ .reg .u64 t; cvta.to.shared.u64 t, %1; cvt.u32.u64 %0, t; }" : "=r"(a) : "l"(p));
    return a;
}
__device__ __forceinline__ void cp16(uint32_t s, const void* g) {
    asm volatile("cp.async.cg.shared.global [%0], [%1], 16;" :: "r"(s), "l"(g));
}
__device__ __forceinline__ void cp_commit() { asm volatile("cp.async.commit_group;"); }

// k-permutation within each 16-half group: logical r -> 4*((r>>1)&3) + 2*((r>>3)&1) + (r&1)
// => thread tg's fragment halfs {2tg, 2tg+1, 2tg+8, 2tg+9} land at phys [4tg, 4tg+4): one LDS.64.
// phys base of logical PAIR index tp (covers logical 2tp,2tp+1), tp in [0,16) per 32-half row span:
__device__ __forceinline__ int pairphys(int tp) {
    return ((tp >> 3) << 4) + ((tp & 3) << 2) + (((tp >> 2) & 1) << 1);
}

__device__ __forceinline__ void mma_f16(float* c, uint2 alo, uint2 ahi, uint2 b) {
    asm volatile(
        "mma.sync.aligned.m16n8k16.row.col.f32.f16.f16.f32 "
        "{%0,%1,%2,%3}, {%4,%5,%6,%7}, {%8,%9}, {%0,%1,%2,%3};"
        : "+f"(c[0]), "+f"(c[1]), "+f"(c[2]), "+f"(c[3])
        : "r"(alo.x), "r"(ahi.x), "r"(alo.y), "r"(ahi.y), "r"(b.x), "r"(b.y));
}

// ---------------- kernel 1: inverse row norms ----------------
__global__ void rownorm_kernel(const float* __restrict__ A, int rows) {
    int row = blockIdx.x * 8 + (threadIdx.x >> 5);
    int l = threadIdx.x & 31;
    if (row >= rows) return;
    const float4* a = reinterpret_cast<const float4*>(A + (size_t)row * DIM);
    float ss = 0.f;
#pragma unroll
    for (int j = 0; j < 4; ++j) {
        float4 v = a[l + 32 * j];
        ss += v.x * v.x + v.y * v.y + v.z * v.z + v.w * v.w;
    }
#pragma unroll
    for (int o = 16; o; o >>= 1) ss += __shfl_xor_sync(0xffffffffu, ss, o);
    if (l == 0) {
        float inv = rsqrtf(fmaxf(ss, 1e-24f));
        if (rows == SIZE) g_minv[row] = inv; else g_xinv[row] = inv;
    }
}

// ---------------- kernel 2: pack x -> fp16, scaled by 8/||x||, k-perm ----------------
__global__ void pack_x_kernel(const float* __restrict__ x) {
    int idx = blockIdx.x * 256 + threadIdx.x;    // BATCH * 256 pair-slots
    int m = idx >> 8, p = idx & 255;             // p = pair index along D
    float2 v = *(const float2*)&x[(size_t)m * DIM + 2 * p];
    float s = 8.0f * g_xinv[m];
    int off = ((p >> 3) << 4) + pairphys(p & 7); // 16-group * 16 halfs + phys pair
    *(__half2*)&g_xp[(size_t)m * DIM + off] = __floats2half2_rn(v.x * s, v.y * s);
}

// ---------------- kernel 3: pack mb -> g_mb1 (row s, perm d) and g_mbT (row d, perm s) ----
__global__ void pack_mb_kernel(const float* __restrict__ mbk) {
    __shared__ float t[32][33];
    int s0 = blockIdx.x << 5, d0 = blockIdx.y << 5;
    int tp = threadIdx.x & 15, ty = threadIdx.x >> 4;   // 256 threads
    int pg = pairphys(tp & 7) + ((tp >> 3) << 4);       // phys pair base within 32 halfs
#pragma unroll
    for (int k = 0; k < 2; ++k) {
        int r = ty + 16 * k;
        float2 v = *(const float2*)&mbk[(size_t)(s0 + r) * DIM + d0 + 2 * tp];
        t[r][2 * tp] = v.x; t[r][2 * tp + 1] = v.y;
        *(__half2*)&g_mb1[(size_t)(s0 + r) * DIM + d0 + pg] = __float22half2_rn(v);
    }
    __syncthreads();
#pragma unroll
    for (int k = 0; k < 2; ++k) {
        int dd = ty + 16 * k;
        float2 v = make_float2(t[2 * tp][dd], t[2 * tp + 1][dd]);
        *(__half2*)&g_mbT[(size_t)(d0 + dd) * SIZE + s0 + pg] = __float22half2_rn(v);
    }
}

// ---------------- shared GEMM machinery (fp16, 3-stage, 1 sync/chunk) ----------------
__device__ __forceinline__ void load_tiles(uint32_t sbase,
                                           const __half* __restrict__ Ag,
                                           const __half* __restrict__ Bg,
                                           size_t arow, size_t brow, int kpos, int tid) {
#pragma unroll
    for (int j = 0; j < 2; ++j) {                 // A: 128 rows x 4 granules = 512
        int i = tid + 256 * j;
        int row = i >> 2, gg = i & 3;
        cp16(sbase + row * RSTRIDE + gg * 16, Ag + (size_t)row * arow + kpos + gg * 8);
    }
#pragma unroll
    for (int j = 0; j < 2; ++j) {                 // B
        int i = tid + 256 * j;
        int row = i >> 2, gg = i & 3;
        cp16(sbase + TILE_BYTES + row * RSTRIDE + gg * 16,
             Bg + (size_t)row * brow + kpos + gg * 8);
    }
}

__device__ __forceinline__ void compute_chunk(const char* __restrict__ As,
                                              const char* __restrict__ Bs,
                                              int wm, int wn, int g, int tg,
                                              float c[2][8][4]) {
    const char* Aw = As + (wm * 32 + g) * RSTRIDE + 8 * tg;
    const char* Bw = Bs + (wn * 64 + g) * RSTRIDE + 8 * tg;
#pragma unroll
    for (int j = 0; j < 2; ++j) {                 // two k16 steps per 32-k chunk
        int off = 32 * j;
        uint2 alo[2], ahi[2], bf[8];
#pragma unroll
        for (int mt = 0; mt < 2; ++mt) {
            alo[mt] = *(const uint2*)(Aw + (mt * 16) * RSTRIDE + off);
            ahi[mt] = *(const uint2*)(Aw + (mt * 16 + 8) * RSTRIDE + off);
        }
#pragma unroll
        for (int nt = 0; nt < 8; ++nt)
            bf[nt] = *(const uint2*)(Bw + (nt * 8) * RSTRIDE + off);
#pragma unroll
        for (int mt = 0; mt < 2; ++mt)
#pragma unroll
            for (int nt = 0; nt < 8; ++nt)
                mma_f16(c[mt][nt], alo[mt], ahi[mt], bf[nt]);
    }
}

__device__ __forceinline__ void gemm_mainloop(char* smc, uint32_t sm32,
                                              const __half* __restrict__ Ag,
                                              const __half* __restrict__ Bg,
                                              size_t arow, size_t brow,
                                              int kbase, int nch, int tid,
                                              int wm, int wn, int g, int tg,
                                              float c[2][8][4]) {
    load_tiles(sm32, Ag, Bg, arow, brow, kbase, tid);
    cp_commit();
    load_tiles(sm32 + STAGE_BYTES, Ag, Bg, arow, brow, kbase + 32, tid);
    cp_commit();
    for (int t = 0; t < nch; ++t) {
        if (t + 1 < nch) asm volatile("cp.async.wait_group 1;");
        else             asm volatile("cp.async.wait_group 0;");
        __syncthreads();   // buffer t ready for all; buffer (t+2)%3 free for all
        if (t + 2 < nch) {
            load_tiles(sm32 + ((t + 2) % 3) * STAGE_BYTES, Ag, Bg, arow, brow,
                       kbase + (t + 2) * 32, tid);
            cp_commit();
        }
        const char* As = smc + (t % 3) * STAGE_BYTES;
        compute_chunk(As, As + TILE_BYTES, wm, wn, g, tg, c);
    }
}

// ---------------- kernel 4: GEMM1 sims + exp epilogue -> g_P (fp16), g_Lpart ----------------
__global__ __launch_bounds__(256, 2) void gemm1_kernel() {
    extern __shared__ char smc[];
    uint32_t sm32 = smem_to_u32(smc);
    int tid = threadIdx.x, lane = tid & 31, w = tid >> 5;
    int wm = w & 3, wn = w >> 2, g = lane >> 2, tg = lane & 3;
    int mblk = blockIdx.x, nblk = blockIdx.y;

    float c[2][8][4];
#pragma unroll
    for (int mt = 0; mt < 2; ++mt)
#pragma unroll
        for (int nt = 0; nt < 8; ++nt)
#pragma unroll
            for (int i = 0; i < 4; ++i) c[mt][nt][i] = 0.f;

    gemm_mainloop(smc, sm32,
                  g_xp + (size_t)mblk * 128 * DIM,
                  g_mb1 + (size_t)nblk * 128 * DIM,
                  DIM, DIM, 0, NCH1, tid, wm, wn, g, tg, c);

    __syncthreads();                         // tiles dead; reuse smem
    float* minv_s = (float*)smc;             // [128]
    float* smL = (float*)(smc + 512);        // [2][128]
    if (tid < 128) minv_s[tid] = g_minv[nblk * 128 + tid];
    __syncthreads();

    float sl[2] = {0.f, 0.f}, sh[2] = {0.f, 0.f};
#pragma unroll
    for (int mt = 0; mt < 2; ++mt) {
        int row0 = mblk * 128 + wm * 32 + mt * 16 + g;
        size_t b0 = (size_t)row0 * SIZE;
        size_t b8 = (size_t)(row0 + 8) * SIZE;
#pragma unroll
        for (int nt = 0; nt < 8; ++nt) {
            int col0 = wn * 64 + nt * 8 + 2 * tg;     // logical col in [0,128)
            float m0 = minv_s[col0], m1 = minv_s[col0 + 1];
            float e0 = __expf(c[mt][nt][0] * m0);
            float e1 = __expf(c[mt][nt][1] * m1);
            float e2 = __expf(c[mt][nt][2] * m0);
            float e3 = __expf(c[mt][nt][3] * m1);
            sl[mt] += e0 + e1;
            sh[mt] += e2 + e3;
            // phys P column (perm16): group = wn*4 + nt/2, in-group = 4tg + 2*(nt&1)
            size_t scol = (size_t)nblk * 128 + ((wn << 2) + (nt >> 1)) * 16
                        + 4 * tg + 2 * (nt & 1);
            *(__half2*)&g_P[b0 + scol] = __floats2half2_rn(e0, e1);
            *(__half2*)&g_P[b8 + scol] = __floats2half2_rn(e2, e3);
        }
    }
#pragma unroll
    for (int mt = 0; mt < 2; ++mt) {
        float vl = sl[mt], vh = sh[mt];
        vl += __shfl_xor_sync(0xffffffffu, vl, 1);
        vl += __shfl_xor_sync(0xffffffffu, vl, 2);
        vh += __shfl_xor_sync(0xffffffffu, vh, 1);
        vh += __shfl_xor_sync(0xffffffffu, vh, 2);
        if (tg == 0) {
            smL[wn * 128 + wm * 32 + mt * 16 + g] = vl;
            smL[wn * 128 + wm * 32 + mt * 16 + g + 8] = vh;
        }
    }
    __syncthreads();
    if (tid < 128)
        g_Lpart[(size_t)nblk * BATCH + mblk * 128 + tid] = smL[tid] + smL[128 + tid];
}

// ---------------- kernel 5: GEMM2 O = P @ mb (split-K partials) ----------------
__global__ __launch_bounds__(256, 2) void gemm2_kernel() {
    extern __shared__ char smc[];
    uint32_t sm32 = smem_to_u32(smc);
    int tid = threadIdx.x, lane = tid & 31, w = tid >> 5;
    int wm = w & 3, wn = w >> 2, g = lane >> 2, tg = lane & 3;
    int mblk = blockIdx.x, nblk = blockIdx.y, sp = blockIdx.z;

    float c[2][8][4];
#pragma unroll
    for (int mt = 0; mt < 2; ++mt)
#pragma unroll
        for (int nt = 0; nt < 8; ++nt)
#pragma unroll
            for (int i = 0; i < 4; ++i) c[mt][nt][i] = 0.f;

    gemm_mainloop(smc, sm32,
                  g_P + (size_t)mblk * 128 * SIZE,
                  g_mbT + (size_t)nblk * 128 * SIZE,
                  SIZE, SIZE, sp * KSPLIT, NCH2, tid, wm, wn, g, tg, c);

#pragma unroll
    for (int mt = 0; mt < 2; ++mt) {
        int b = mblk * 128 + wm * 32 + mt * 16 + g;
#pragma unroll
        for (int nt = 0; nt < 8; ++nt) {
            int d = nblk * 128 + wn * 64 + nt * 8 + 2 * tg;
            float* dst = &g_part2[((size_t)sp * BATCH + b) * DIM + d];
            *(float2*)dst = make_float2(c[mt][nt][0], c[mt][nt][1]);
            *(float2*)(dst + (size_t)8 * DIM) = make_float2(c[mt][nt][2], c[mt][nt][3]);
        }
    }
}

// ---------------- kernel 6: combine split-K partials, divide by L ----------------
__global__ void combine_kernel(float* __restrict__ out) {
    int b = blockIdx.x, tid = threadIdx.x;   // 128 threads
    __shared__ float red[128];
    float ls = 0.f;
#pragma unroll
    for (int k = 0; k < 4; ++k) ls += g_Lpart[(size_t)(k * 128 + tid) * BATCH + b];
    red[tid] = ls;
    __syncthreads();
    for (int o = 64; o; o >>= 1) { if (tid < o) red[tid] += red[tid + o]; __syncthreads(); }
    float invL = 1.0f / red[0];
    int d = tid * 4;
    float4 acc = make_float4(0.f, 0.f, 0.f, 0.f);
#pragma unroll
    for (int sp = 0; sp < SPLITS; ++sp) {
        const float4 v = *(const float4*)&g_part2[((size_t)sp * BATCH + b) * DIM + d];
        acc.x += v.x; acc.y += v.y; acc.z += v.z; acc.w += v.w;
    }
    acc.x *= invL; acc.y *= invL; acc.z *= invL; acc.w *= invL;
    *(float4*)&out[(size_t)b * DIM + d] = acc;
}

// ---------------------------------------------------------------------------
extern "C" void kernel_launch(void* const* d_in, const int* in_sizes, int n_in,
                              void* d_out, int out_size) {
    const float* x = (const float*)d_in[0];
    const float* mb = (const float*)d_in[1];
    float* out = (float*)d_out;
    (void)in_sizes; (void)n_in; (void)out_size;

    cudaFuncSetAttribute(gemm1_kernel, cudaFuncAttributeMaxDynamicSharedMemorySize, SMEM_BYTES);
    cudaFuncSetAttribute(gemm2_kernel, cudaFuncAttributeMaxDynamicSharedMemorySize, SMEM_BYTES);

    rownorm_kernel<<<SIZE / 8, 256>>>(mb, SIZE);
    rownorm_kernel<<<BATCH / 8, 256>>>(x, BATCH);
    pack_x_kernel<<<BATCH, 256>>>(x);
    pack_mb_kernel<<<dim3(SIZE / 32, DIM / 32), 256>>>(mb);
    gemm1_kernel<<<dim3(BATCH / 128, SIZE / 128), 256, SMEM_BYTES>>>();
    gemm2_kernel<<<dim3(BATCH / 128, DIM / 128, SPLITS), 256, SMEM_BYTES>>>();
    combine_kernel<<<BATCH, 128>>>(out);
}

// round 7
// speedup vs baseline: 12.6060x; 1.1505x over previous
#include <cuda_runtime.h>
#include <cuda_fp16.h>
#include <cstdint>
#include <cstddef>

#define BATCH 1024
#define SIZE  65536
#define DIM   512
#define SPLITS 32
#define KSPLIT (SIZE / SPLITS)        // 2048

#define RBYTES 64                     // dense 32-half rows, 16B-XOR swizzled
#define TILE_BYTES (128 * RBYTES)     // 8192
#define STAGE_BYTES (2 * TILE_BYTES)  // 16384 (A+B)
#define NSTAGE 4
#define SMEM_BYTES (NSTAGE * STAGE_BYTES) // 65536
#define THREADS 128
#define NCH1 (DIM / 32)               // 16
#define NCH2 (KSPLIT / 32)            // 64

// ---------------- device scratch (allocation-free) ----------------
__device__ float g_minv[SIZE];
__device__ float g_xinv[BATCH];
__device__ __align__(16) __half g_xp[(size_t)BATCH * DIM];     //   1 MB
__device__ __align__(16) __half g_mb1[(size_t)SIZE * DIM];     //  64 MB (GEMM1 B)
__device__ __align__(16) __half g_mbT[(size_t)DIM * SIZE];     //  64 MB (GEMM2 B)
__device__ __align__(16) __half g_P[(size_t)BATCH * SIZE];     // 128 MB (GEMM2 A)
__device__ float g_Lpart[(size_t)(SIZE / 128) * BATCH];        //   2 MB
__device__ float g_part2[(size_t)SPLITS * BATCH * DIM];        //  64 MB

// ---------------- helpers ----------------
__device__ __forceinline__ uint32_t smem_to_u32(const void* p) {
    uint32_t a;
    asm("{ .reg .u64 t; cvta.to.shared.u64 t, %1; cvt.u32.u64 %0, t; }" : "=r"(a) : "l"(p));
    return a;
}
__device__ __forceinline__ void cp16(uint32_t s, const void* g) {
    asm volatile("cp.async.cg.shared.global [%0], [%1], 16;" :: "r"(s), "l"(g));
}
__device__ __forceinline__ void cp_commit() { asm volatile("cp.async.commit_group;"); }

// k-permutation within each 16-half group: thread tg's fragment halfs
// {2tg,2tg+1,2tg+8,2tg+9} land at phys [4tg,4tg+4): one LDS.64 per fragment.
__device__ __forceinline__ int pairphys(int tp) {
    return ((tp >> 3) << 4) + ((tp & 3) << 2) + (((tp >> 2) & 1) << 1);
}

__device__ __forceinline__ void mma_f16(float* c, uint2 alo, uint2 ahi, uint2 b) {
    asm volatile(
        "mma.sync.aligned.m16n8k16.row.col.f32.f16.f16.f32 "
        "{%0,%1,%2,%3}, {%4,%5,%6,%7}, {%8,%9}, {%0,%1,%2,%3};"
        : "+f"(c[0]), "+f"(c[1]), "+f"(c[2]), "+f"(c[3])
        : "r"(alo.x), "r"(ahi.x), "r"(alo.y), "r"(ahi.y), "r"(b.x), "r"(b.y));
}

// ---------------- kernel 1: inverse row norms ----------------
__global__ void rownorm_kernel(const float* __restrict__ A, int rows) {
    int row = blockIdx.x * 8 + (threadIdx.x >> 5);
    int l = threadIdx.x & 31;
    if (row >= rows) return;
    const float4* a = reinterpret_cast<const float4*>(A + (size_t)row * DIM);
    float ss = 0.f;
#pragma unroll
    for (int j = 0; j < 4; ++j) {
        float4 v = a[l + 32 * j];
        ss += v.x * v.x + v.y * v.y + v.z * v.z + v.w * v.w;
    }
#pragma unroll
    for (int o = 16; o; o >>= 1) ss += __shfl_xor_sync(0xffffffffu, ss, o);
    if (l == 0) {
        float inv = rsqrtf(fmaxf(ss, 1e-24f));
        if (rows == SIZE) g_minv[row] = inv; else g_xinv[row] = inv;
    }
}

// ---------------- kernel 2: pack x -> fp16, scaled by 8/||x||, k-perm ----------------
__global__ void pack_x_kernel(const float* __restrict__ x) {
    int idx = blockIdx.x * 256 + threadIdx.x;    // BATCH * 256 pair-slots
    int m = idx >> 8, p = idx & 255;
    float2 v = *(const float2*)&x[(size_t)m * DIM + 2 * p];
    float s = 8.0f * g_xinv[m];
    int off = ((p >> 3) << 4) + pairphys(p & 7);
    *(__half2*)&g_xp[(size_t)m * DIM + off] = __floats2half2_rn(v.x * s, v.y * s);
}

// ---------------- kernel 3: pack mb -> g_mb1 and g_mbT (fp16, k-perm) ----------------
__global__ void pack_mb_kernel(const float* __restrict__ mbk) {
    __shared__ float t[32][33];
    int s0 = blockIdx.x << 5, d0 = blockIdx.y << 5;
    int tp = threadIdx.x & 15, ty = threadIdx.x >> 4;   // 256 threads
    int pg = pairphys(tp & 7) + ((tp >> 3) << 4);
#pragma unroll
    for (int k = 0; k < 2; ++k) {
        int r = ty + 16 * k;
        float2 v = *(const float2*)&mbk[(size_t)(s0 + r) * DIM + d0 + 2 * tp];
        t[r][2 * tp] = v.x; t[r][2 * tp + 1] = v.y;
        *(__half2*)&g_mb1[(size_t)(s0 + r) * DIM + d0 + pg] = __float22half2_rn(v);
    }
    __syncthreads();
#pragma unroll
    for (int k = 0; k < 2; ++k) {
        int dd = ty + 16 * k;
        float2 v = make_float2(t[2 * tp][dd], t[2 * tp + 1][dd]);
        *(__half2*)&g_mbT[(size_t)(d0 + dd) * SIZE + s0 + pg] = __float22half2_rn(v);
    }
}

// ---------------- GEMM machinery: 4 warps, warp tile 64x64, XOR-swizzled smem ----------
__device__ __forceinline__ void load_tiles(uint32_t sbase,
                                           const __half* __restrict__ Ag,
                                           const __half* __restrict__ Bg,
                                           size_t arow, size_t brow, int kpos, int tid) {
#pragma unroll
    for (int j = 0; j < 4; ++j) {                 // A: 128 rows x 4 granules
        int i = tid + THREADS * j;
        int row = i >> 2, gg = i & 3;
        cp16(sbase + row * RBYTES + ((gg ^ (row & 3)) << 4),
             Ag + (size_t)row * arow + kpos + gg * 8);
    }
#pragma unroll
    for (int j = 0; j < 4; ++j) {                 // B
        int i = tid + THREADS * j;
        int row = i >> 2, gg = i & 3;
        cp16(sbase + TILE_BYTES + row * RBYTES + ((gg ^ (row & 3)) << 4),
             Bg + (size_t)row * brow + kpos + gg * 8);
    }
}

__device__ __forceinline__ void compute_chunk(const char* __restrict__ As,
                                              const char* __restrict__ Bs,
                                              int wm, int wn, int g, int tg,
                                              float c[4][8][4]) {
    const char* Aw = As + (wm * 64 + g) * RBYTES;
    const char* Bw = Bs + (wn * 64 + g) * RBYTES;
    const int gx = g & 3;
#pragma unroll
    for (int j = 0; j < 2; ++j) {                 // two k16 steps per 32-k chunk
        // fragment byte offset within row: slot (tg>>1)+2j, XOR row&3 (= g&3)
        int boff = ((((tg >> 1) + 2 * j) ^ gx) << 4) + ((tg & 1) << 3);
        uint2 alo[4], ahi[4], bf[8];
#pragma unroll
        for (int mt = 0; mt < 4; ++mt) {
            alo[mt] = *(const uint2*)(Aw + (mt * 16) * RBYTES + boff);
            ahi[mt] = *(const uint2*)(Aw + (mt * 16 + 8) * RBYTES + boff);
        }
#pragma unroll
        for (int nt = 0; nt < 8; ++nt)
            bf[nt] = *(const uint2*)(Bw + (nt * 8) * RBYTES + boff);
#pragma unroll
        for (int mt = 0; mt < 4; ++mt)
#pragma unroll
            for (int nt = 0; nt < 8; ++nt)
                mma_f16(c[mt][nt], alo[mt], ahi[mt], bf[nt]);
    }
}

__device__ __forceinline__ void gemm_mainloop(char* smc, uint32_t sm32,
                                              const __half* __restrict__ Ag,
                                              const __half* __restrict__ Bg,
                                              size_t arow, size_t brow,
                                              int kbase, int nch, int tid,
                                              int wm, int wn, int g, int tg,
                                              float c[4][8][4]) {
#pragma unroll
    for (int s = 0; s < 3; ++s) {
        load_tiles(sm32 + s * STAGE_BYTES, Ag, Bg, arow, brow, kbase + s * 32, tid);
        cp_commit();
    }
    for (int t = 0; t < nch; ++t) {
        if (t + 3 < nch) asm volatile("cp.async.wait_group 2;");
        else             asm volatile("cp.async.wait_group 0;");
        __syncthreads();   // stage t ready; stage (t+3)&3 = (t-1)&3 free
        if (t + 3 < nch) {
            load_tiles(sm32 + ((t + 3) & 3) * STAGE_BYTES, Ag, Bg, arow, brow,
                       kbase + (t + 3) * 32, tid);
            cp_commit();
        }
        const char* As = smc + (t & 3) * STAGE_BYTES;
        compute_chunk(As, As + TILE_BYTES, wm, wn, g, tg, c);
    }
}

// ---------------- kernel 4: GEMM1 sims + exp epilogue -> g_P (fp16), g_Lpart ------------
__global__ __launch_bounds__(THREADS, 2) void gemm1_kernel() {
    extern __shared__ char smc[];
    uint32_t sm32 = smem_to_u32(smc);
    int tid = threadIdx.x, lane = tid & 31, w = tid >> 5;
    int wm = w & 1, wn = w >> 1, g = lane >> 2, tg = lane & 3;
    int mblk = blockIdx.x, nblk = blockIdx.y;

    float c[4][8][4];
#pragma unroll
    for (int mt = 0; mt < 4; ++mt)
#pragma unroll
        for (int nt = 0; nt < 8; ++nt)
#pragma unroll
            for (int i = 0; i < 4; ++i) c[mt][nt][i] = 0.f;

    gemm_mainloop(smc, sm32,
                  g_xp + (size_t)mblk * 128 * DIM,
                  g_mb1 + (size_t)nblk * 128 * DIM,
                  DIM, DIM, 0, NCH1, tid, wm, wn, g, tg, c);

    __syncthreads();                         // tiles dead; reuse smem
    float* minv_s = (float*)smc;             // [128]
    float* smL = (float*)(smc + 512);        // [2][128]
    if (tid < 128) minv_s[tid] = g_minv[nblk * 128 + tid];
    __syncthreads();

    float sl[4], sh[4];
#pragma unroll
    for (int mt = 0; mt < 4; ++mt) { sl[mt] = 0.f; sh[mt] = 0.f; }
#pragma unroll
    for (int mt = 0; mt < 4; ++mt) {
        int row0 = mblk * 128 + wm * 64 + mt * 16 + g;
        size_t b0 = (size_t)row0 * SIZE;
        size_t b8 = (size_t)(row0 + 8) * SIZE;
#pragma unroll
        for (int nt = 0; nt < 8; ++nt) {
            int col0 = wn * 64 + nt * 8 + 2 * tg;     // logical col
            float m0 = minv_s[col0], m1 = minv_s[col0 + 1];
            float e0 = __expf(c[mt][nt][0] * m0);
            float e1 = __expf(c[mt][nt][1] * m1);
            float e2 = __expf(c[mt][nt][2] * m0);
            float e3 = __expf(c[mt][nt][3] * m1);
            sl[mt] += e0 + e1;
            sh[mt] += e2 + e3;
            // phys P column (perm16): group = wn*4 + nt/2, in-group = 4tg + 2*(nt&1)
            size_t scol = (size_t)nblk * 128 + ((wn << 2) + (nt >> 1)) * 16
                        + 4 * tg + 2 * (nt & 1);
            *(__half2*)&g_P[b0 + scol] = __floats2half2_rn(e0, e1);
            *(__half2*)&g_P[b8 + scol] = __floats2half2_rn(e2, e3);
        }
    }
#pragma unroll
    for (int mt = 0; mt < 4; ++mt) {
        float vl = sl[mt], vh = sh[mt];
        vl += __shfl_xor_sync(0xffffffffu, vl, 1);
        vl += __shfl_xor_sync(0xffffffffu, vl, 2);
        vh += __shfl_xor_sync(0xffffffffu, vh, 1);
        vh += __shfl_xor_sync(0xffffffffu, vh, 2);
        if (tg == 0) {
            smL[wn * 128 + wm * 64 + mt * 16 + g] = vl;
            smL[wn * 128 + wm * 64 + mt * 16 + g + 8] = vh;
        }
    }
    __syncthreads();
    if (tid < 128)
        g_Lpart[(size_t)nblk * BATCH + mblk * 128 + tid] = smL[tid] + smL[128 + tid];
}

// ---------------- kernel 5: GEMM2 O = P @ mb (split-K partials) ----------------
__global__ __launch_bounds__(THREADS, 2) void gemm2_kernel() {
    extern __shared__ char smc[];
    uint32_t sm32 = smem_to_u32(smc);
    int tid = threadIdx.x, lane = tid & 31, w = tid >> 5;
    int wm = w & 1, wn = w >> 1, g = lane >> 2, tg = lane & 3;
    int mblk = blockIdx.x, nblk = blockIdx.y, sp = blockIdx.z;

    float c[4][8][4];
#pragma unroll
    for (int mt = 0; mt < 4; ++mt)
#pragma unroll
        for (int nt = 0; nt < 8; ++nt)
#pragma unroll
            for (int i = 0; i < 4; ++i) c[mt][nt][i] = 0.f;

    gemm_mainloop(smc, sm32,
                  g_P + (size_t)mblk * 128 * SIZE,
                  g_mbT + (size_t)nblk * 128 * SIZE,
                  SIZE, SIZE, sp * KSPLIT, NCH2, tid, wm, wn, g, tg, c);

#pragma unroll
    for (int mt = 0; mt < 4; ++mt) {
        int b = mblk * 128 + wm * 64 + mt * 16 + g;
#pragma unroll
        for (int nt = 0; nt < 8; ++nt) {
            int d = nblk * 128 + wn * 64 + nt * 8 + 2 * tg;
            float* dst = &g_part2[((size_t)sp * BATCH + b) * DIM + d];
            *(float2*)dst = make_float2(c[mt][nt][0], c[mt][nt][1]);
            *(float2*)(dst + (size_t)8 * DIM) = make_float2(c[mt][nt][2], c[mt][nt][3]);
        }
    }
}

// ---------------- kernel 6: combine split-K partials, divide by L ----------------
__global__ void combine_kernel(float* __restrict__ out) {
    int b = blockIdx.x, tid = threadIdx.x;   // 128 threads
    __shared__ float red[128];
    float ls = 0.f;
#pragma unroll
    for (int k = 0; k < 4; ++k) ls += g_Lpart[(size_t)(k * 128 + tid) * BATCH + b];
    red[tid] = ls;
    __syncthreads();
    for (int o = 64; o; o >>= 1) { if (tid < o) red[tid] += red[tid + o]; __syncthreads(); }
    float invL = 1.0f / red[0];
    int d = tid * 4;
    float4 acc = make_float4(0.f, 0.f, 0.f, 0.f);
#pragma unroll
    for (int sp = 0; sp < SPLITS; ++sp) {
        const float4 v = *(const float4*)&g_part2[((size_t)sp * BATCH + b) * DIM + d];
        acc.x += v.x; acc.y += v.y; acc.z += v.z; acc.w += v.w;
    }
    acc.x *= invL; acc.y *= invL; acc.z *= invL; acc.w *= invL;
    *(float4*)&out[(size_t)b * DIM + d] = acc;
}

// ---------------------------------------------------------------------------
extern "C" void kernel_launch(void* const* d_in, const int* in_sizes, int n_in,
                              void* d_out, int out_size) {
    const float* x = (const float*)d_in[0];
    const float* mb = (const float*)d_in[1];
    float* out = (float*)d_out;
    (void)in_sizes; (void)n_in; (void)out_size;

    cudaFuncSetAttribute(gemm1_kernel, cudaFuncAttributeMaxDynamicSharedMemorySize, SMEM_BYTES);
    cudaFuncSetAttribute(gemm2_kernel, cudaFuncAttributeMaxDynamicSharedMemorySize, SMEM_BYTES);

    rownorm_kernel<<<SIZE / 8, 256>>>(mb, SIZE);
    rownorm_kernel<<<BATCH / 8, 256>>>(x, BATCH);
    pack_x_kernel<<<BATCH, 256>>>(x);
    pack_mb_kernel<<<dim3(SIZE / 32, DIM / 32), 256>>>(mb);
    gemm1_kernel<<<dim3(BATCH / 128, SIZE / 128), THREADS, SMEM_BYTES>>>();
    gemm2_kernel<<<dim3(BATCH / 128, DIM / 128, SPLITS), THREADS, SMEM_BYTES>>>();
    combine_kernel<<<BATCH, 128>>>(out);
}